// round 6
// baseline (speedup 1.0000x reference)
#include <cuda_runtime.h>
#include <cuda_bf16.h>
#include <cooperative_groups.h>

namespace cg = cooperative_groups;

#define D    256
#define F    1024
#define NL   4
#define NC   10
#define CS   8      // cluster size (ranks per batch element)
#define TPB  512

// two-value block reduction (sum, sumsq) over 512 threads (16 warps)
__device__ __forceinline__ float2 blockReduceSum2(float a, float b, float2* red2) {
    #pragma unroll
    for (int o = 16; o > 0; o >>= 1) {
        a += __shfl_xor_sync(0xffffffffu, a, o);
        b += __shfl_xor_sync(0xffffffffu, b, o);
    }
    int wid = threadIdx.x >> 5;
    if ((threadIdx.x & 31) == 0) red2[wid] = make_float2(a, b);
    __syncthreads();
    if (threadIdx.x < 16) {
        float2 t = red2[threadIdx.x];
        #pragma unroll
        for (int o = 8; o > 0; o >>= 1) {
            t.x += __shfl_xor_sync(0xffffu, t.x, o);
            t.y += __shfl_xor_sync(0xffffu, t.y, o);
        }
        if (threadIdx.x == 0) red2[0] = t;
    }
    __syncthreads();
    float2 r = red2[0];
    __syncthreads();
    return r;
}

__device__ __forceinline__ float gelu_tanh(float x) {
    const float c = 0.7978845608028654f;   // sqrt(2/pi)
    float u = c * (x + 0.044715f * x * x * x);
    return 0.5f * x * (1.0f + tanhf(u));
}

__global__ void __launch_bounds__(TPB, 1) __cluster_dims__(CS, 1, 1)
performer_cls_kernel(const int*   __restrict__ xx,
                     const float* __restrict__ emb_tok,
                     const float* __restrict__ emb_pos,
                     const float* __restrict__ ln1_s,
                     const float* __restrict__ ln1_b,
                     const float* __restrict__ wv,
                     const float* __restrict__ wo,
                     const float* __restrict__ bo,
                     const float* __restrict__ ln2_s,
                     const float* __restrict__ ln2_b,
                     const float* __restrict__ w1,
                     const float* __restrict__ b1,
                     const float* __restrict__ w2,
                     const float* __restrict__ b2,
                     const float* __restrict__ wcls,
                     const float* __restrict__ bcls,
                     float* __restrict__ out,
                     int N)
{
    __shared__ float  sh_h[D];       // residual stream (replicated per rank)
    __shared__ float  sh_y[D];       // LN output
    __shared__ float  sh_g[F];       // v0 (first 256) / MLP hidden (full)
    __shared__ float  sh_c[128];     // my output chunk staging
    __shared__ float  ps[2112];      // split-K partials (A/C: 32x65; B: 528 float4)
    __shared__ float2 red2[16];

    cg::cluster_group cluster = cg::this_cluster();
    const int tid = threadIdx.x;
    const int r   = (int)cluster.block_rank();       // 0..7
    const int b   = blockIdx.x >> 3;                 // batch element

    // A/C-stage roles: 8 col-threads x 4 cols = 32 cols; 64 K-slices
    const int c4  = tid & 7;
    const int ks  = tid >> 3;                        // 0..63
    // B-stage roles: 32 col-threads x 4 cols = 128 cols; 16 K-slices
    const int c4b = tid & 31;
    const int ksb = tid >> 5;                        // 0..15
    // broadcast roles
    const int p_dst  = tid >> 5;                     // rank 0..15? no: 0..7 for tid<256
    const int p_lane = tid & 31;
    const int q_dst  = tid >> 6;                     // 0..7 (512 threads)
    const int q_lane = tid & 63;

    const int j0  = r * 32;                          // my 32-col tile (A/C)
    const int j0b = r * 128;                         // my 128-col tile (B)

    // ---- init: every rank computes full h0 locally ----
    if (tid < D) {
        const int tok = xx[b * N];
        sh_h[tid] = emb_tok[tok * D + tid] + emb_pos[tid];
    }
    __syncthreads();

    for (int l = 0; l < NL; ++l) {
        // ======== stage A1: v0 = LN1(h) @ wv (my 32 cols) ========
        float4 wpre[4];                              // A2 prefetch (wo)
        {
            float v = (tid < D) ? sh_h[tid] : 0.0f;
            float2 ss = blockReduceSum2(v, v * v, red2);
            float mu  = ss.x * (1.0f / D);
            float var = ss.y * (1.0f / D) - mu * mu;
            float inv = rsqrtf(var + 1e-5f);
            if (tid < D)
                sh_y[tid] = (v - mu) * inv * ln1_s[l * D + tid] + ln1_b[l * D + tid];
            __syncthreads();

            const float* W = wv + (size_t)l * D * D;
            float4 a = make_float4(0.f, 0.f, 0.f, 0.f);
            #pragma unroll
            for (int i = 0; i < 4; ++i) {
                int k = ks * 4 + i;
                float4 w = *((const float4*)(W + (size_t)k * D + j0) + c4);
                float yk = sh_y[k];
                a.x = fmaf(yk, w.x, a.x); a.y = fmaf(yk, w.y, a.y);
                a.z = fmaf(yk, w.z, a.z); a.w = fmaf(yk, w.w, a.w);
            }
            ps[(c4 * 4 + 0) * 65 + ks] = a.x;
            ps[(c4 * 4 + 1) * 65 + ks] = a.y;
            ps[(c4 * 4 + 2) * 65 + ks] = a.z;
            ps[(c4 * 4 + 3) * 65 + ks] = a.w;
            __syncthreads();
            if (tid < 32) {
                float acc = 0.0f;
                #pragma unroll
                for (int s = 0; s < 64; ++s) acc += ps[tid * 65 + s];
                sh_c[tid] = acc;
            }
            __syncthreads();
            if (tid < 256) {   // broadcast my v0 chunk to all ranks' sh_g
                float* dst = cluster.map_shared_rank(sh_g, p_dst);
                dst[j0 + p_lane] = sh_c[p_lane];
            }
            // prefetch A2 weights across the barrier
            const float* W2p = wo + (size_t)l * D * D;
            #pragma unroll
            for (int i = 0; i < 4; ++i)
                wpre[i] = *((const float4*)(W2p + (size_t)(ks * 4 + i) * D + j0) + c4);
        }
        cluster.sync();

        // ======== stage A2: h += v0 @ wo + bo ========
        {
            float4 a = make_float4(0.f, 0.f, 0.f, 0.f);
            #pragma unroll
            for (int i = 0; i < 4; ++i) {
                float yk = sh_g[ks * 4 + i];         // v0
                a.x = fmaf(yk, wpre[i].x, a.x); a.y = fmaf(yk, wpre[i].y, a.y);
                a.z = fmaf(yk, wpre[i].z, a.z); a.w = fmaf(yk, wpre[i].w, a.w);
            }
            ps[(c4 * 4 + 0) * 65 + ks] = a.x;
            ps[(c4 * 4 + 1) * 65 + ks] = a.y;
            ps[(c4 * 4 + 2) * 65 + ks] = a.z;
            ps[(c4 * 4 + 3) * 65 + ks] = a.w;
            __syncthreads();
            if (tid < 32) {
                float acc = bo[l * D + j0 + tid];
                #pragma unroll
                for (int s = 0; s < 64; ++s) acc += ps[tid * 65 + s];
                sh_c[tid] = sh_h[j0 + tid] + acc;    // new h chunk
            }
            __syncthreads();
            if (tid < 256) {
                float* dst = cluster.map_shared_rank(sh_h, p_dst);
                dst[j0 + p_lane] = sh_c[p_lane];
            }
        }
        cluster.sync();

        // ======== stage B: hidden = gelu(LN2(h) @ w1 + b1) (my 128 cols) ====
        {
            float v = (tid < D) ? sh_h[tid] : 0.0f;
            float2 ss = blockReduceSum2(v, v * v, red2);
            float mu  = ss.x * (1.0f / D);
            float var = ss.y * (1.0f / D) - mu * mu;
            float inv = rsqrtf(var + 1e-5f);
            if (tid < D)
                sh_y[tid] = (v - mu) * inv * ln2_s[l * D + tid] + ln2_b[l * D + tid];
            __syncthreads();

            const float* W1 = w1 + (size_t)l * D * F;
            float4 a = make_float4(0.f, 0.f, 0.f, 0.f);
            #pragma unroll
            for (int i = 0; i < 16; ++i) {
                int k = ksb * 16 + i;
                float4 w = *((const float4*)(W1 + (size_t)k * F + j0b) + c4b);
                float yk = sh_y[k];
                a.x = fmaf(yk, w.x, a.x); a.y = fmaf(yk, w.y, a.y);
                a.z = fmaf(yk, w.z, a.z); a.w = fmaf(yk, w.w, a.w);
            }
            ((float4*)ps)[ksb * 33 + c4b] = a;       // conflict-free float4 tile
            __syncthreads();
            if (tid < 128) {
                float acc = b1[l * F + j0b + tid];
                #pragma unroll
                for (int s = 0; s < 16; ++s) acc += ps[s * 132 + tid];
                sh_c[tid] = gelu_tanh(acc);
            }
            __syncthreads();
            {   // broadcast my 128-float hidden chunk (all 512 threads, 2 each)
                float* dst = cluster.map_shared_rank(sh_g, q_dst);
                dst[j0b + q_lane]      = sh_c[q_lane];
                dst[j0b + 64 + q_lane] = sh_c[64 + q_lane];
            }
        }
        cluster.sync();

        // ======== stage C: h += hidden @ w2 + b2 ========
        {
            const float* W2 = w2 + (size_t)l * F * D;
            float4 a = make_float4(0.f, 0.f, 0.f, 0.f);
            #pragma unroll
            for (int i = 0; i < 16; ++i) {
                int k = ks * 16 + i;
                float4 w = *((const float4*)(W2 + (size_t)k * D + j0) + c4);
                float yk = sh_g[k];                  // hidden
                a.x = fmaf(yk, w.x, a.x); a.y = fmaf(yk, w.y, a.y);
                a.z = fmaf(yk, w.z, a.z); a.w = fmaf(yk, w.w, a.w);
            }
            ps[(c4 * 4 + 0) * 65 + ks] = a.x;
            ps[(c4 * 4 + 1) * 65 + ks] = a.y;
            ps[(c4 * 4 + 2) * 65 + ks] = a.z;
            ps[(c4 * 4 + 3) * 65 + ks] = a.w;
            __syncthreads();
            if (tid < 32) {
                float acc = b2[l * D + j0 + tid];
                #pragma unroll
                for (int s = 0; s < 64; ++s) acc += ps[tid * 65 + s];
                sh_c[tid] = sh_h[j0 + tid] + acc;
            }
            __syncthreads();
            if (tid < 256) {
                float* dst = cluster.map_shared_rank(sh_h, p_dst);
                dst[j0 + p_lane] = sh_c[p_lane];
            }
        }
        cluster.sync();
    }

    // ======== classifier (rank 0 of each cluster) ========
    if (r == 0) {
        if (tid < 160) {
            const int c = tid >> 4;          // class 0..9
            const int s = tid & 15;          // 16 K-slices of 16
            float acc = 0.0f;
            #pragma unroll
            for (int i = 0; i < 16; ++i) {
                int k = s * 16 + i;
                acc = fmaf(sh_h[k], wcls[k * NC + c], acc);
            }
            ps[c * 17 + s] = acc;
        }
        __syncthreads();
        if (tid < NC) {
            float acc = bcls[tid];
            #pragma unroll
            for (int s = 0; s < 16; ++s) acc += ps[tid * 17 + s];
            out[b * NC + tid] = acc;
        }
    }
}

extern "C" void kernel_launch(void* const* d_in, const int* in_sizes, int n_in,
                              void* d_out, int out_size)
{
    const int*   xx      = (const int*)  d_in[0];
    const float* emb_tok = (const float*)d_in[1];
    const float* emb_pos = (const float*)d_in[2];
    const float* ln1_s   = (const float*)d_in[4];
    const float* ln1_b   = (const float*)d_in[5];
    const float* wv      = (const float*)d_in[8];
    const float* wo      = (const float*)d_in[9];
    const float* bo      = (const float*)d_in[10];
    const float* ln2_s   = (const float*)d_in[11];
    const float* ln2_b   = (const float*)d_in[12];
    const float* w1      = (const float*)d_in[13];
    const float* b1      = (const float*)d_in[14];
    const float* w2      = (const float*)d_in[15];
    const float* b2      = (const float*)d_in[16];
    const float* wcls    = (const float*)d_in[17];
    const float* bcls    = (const float*)d_in[18];
    float* out = (float*)d_out;

    const int B = out_size / NC;      // 16
    const int N = in_sizes[0] / B;    // 4096

    performer_cls_kernel<<<B * CS, TPB>>>(xx, emb_tok, emb_pos, ln1_s, ln1_b,
                                          wv, wo, bo, ln2_s, ln2_b,
                                          w1, b1, w2, b2, wcls, bcls, out, N);
}